// round 15
// baseline (speedup 1.0000x reference)
#include <cuda_runtime.h>

#define B 256
#define M 2048
#define E 128
#define IN_D 512
#define Q_D 512
#define OUT_D 512
#define H 64

// output layout (depth-first flatten of ((wr, nww, nu), output, new_memory))
#define OFF_WR  ((size_t)0)
#define OFF_NWW ((size_t)B*M)
#define OFF_NU  ((size_t)2*B*M)
#define OFF_OUT ((size_t)3*B*M)
#define OFF_NM  ((size_t)3*B*M + (size_t)B*OUT_D)

// scratch (device globals: no allocation allowed)
__device__ float g_emb[B*E];
__device__ float g_avec[B*E];
__device__ float g_bvec[B*E];
__device__ float g_ce[B];
__device__ float g_scores[B*M];
__device__ float g_rbase[B*M];
__device__ float g_pooled[B*E];
__device__ unsigned int g_done1[B];
__device__ unsigned int g_done2[B];

__device__ __forceinline__ float warp_dot(const float* __restrict__ w,
                                          const float* __restrict__ s,
                                          int n, int lane) {
    float acc = 0.f;
    for (int i = lane; i < n; i += 32) acc += w[i]*s[i];
    #pragma unroll
    for (int o = 16; o > 0; o >>= 1) acc += __shfl_down_sync(0xffffffffu, acc, o);
    return acc;  // valid on lane 0
}

// ---------------------------------------------------------------------------
// Kernel 0: per-batch small GEMMs -> g_emb, g_avec, g_bvec, g_ce; zero pooled
// and the ticket counters (replay-safe).
// ---------------------------------------------------------------------------
__global__ void k_pre(const float* __restrict__ x, const float* __restrict__ query,
                      const float* __restrict__ Iw, const float* __restrict__ Ib,
                      const float* __restrict__ W1w, const float* __restrict__ W1b,
                      const float* __restrict__ W2w,
                      const float* __restrict__ R1w, const float* __restrict__ R1b,
                      const float* __restrict__ R2w) {
    int b = blockIdx.x, t = threadIdx.x;      // 128 threads, 4 warps
    int lane = t & 31, wid = t >> 5;
    __shared__ float sx[IN_D], sq[Q_D], semb[E], sWi[H], sRq[H], sred[E];
    for (int i = t; i < IN_D; i += 128) sx[i] = x[(size_t)b*IN_D + i];
    for (int i = t; i < Q_D;  i += 128) sq[i] = query[(size_t)b*Q_D + i];
    if (t < E) g_pooled[(size_t)b*E + t] = 0.f;
    if (t == 0) { g_done1[b] = 0u; g_done2[b] = 0u; }
    __syncthreads();
    for (int o = wid; o < E; o += 4) {
        float d = warp_dot(Iw + (size_t)o*IN_D, sx, IN_D, lane);
        if (lane == 0) { d += Ib[o]; semb[o] = d; g_emb[(size_t)b*E + o] = d; }
    }
    __syncthreads();
    for (int o = wid; o < H; o += 4) {
        float d = warp_dot(W1w + (size_t)o*E, semb, E, lane);
        if (lane == 0) sWi[o] = d + W1b[o];
        float d2 = warp_dot(R1w + (size_t)o*Q_D, sq, Q_D, lane);
        if (lane == 0) sRq[o] = d2 + R1b[o];
    }
    __syncthreads();
    {
        float av = 0.f, bv = 0.f;
        #pragma unroll 8
        for (int h = 0; h < H; h++) {
            av += sWi[h]*W2w[(size_t)h*E + t];
            bv += sRq[h]*R2w[(size_t)h*E + t];
        }
        g_avec[(size_t)b*E + t] = av;
        g_bvec[(size_t)b*E + t] = bv;
        sred[t] = bv*semb[t];
    }
    __syncthreads();
    for (int s = 64; s > 0; s >>= 1) { if (t < s) sred[t] += sred[t+s]; __syncthreads(); }
    if (t == 0) g_ce[b] = sred[0];
}

// ---------------------------------------------------------------------------
// Kernel 1: streaming dots + (last block per batch) allocation/softmax tail.
// Grid (16, B), 256 thr. Dots phase = R14 shape. After a block's chunk is
// written + fenced, it takes a ticket; ticket 15 runs the per-batch tail:
// usage update, EXACT stable bucket argsort (64-bit key (bits<<11)|idx ==
// jnp.argsort), cumprod (hand shuffle scans), alloc, two softmaxes ->
// NU/NWW/WR. Tail overlaps other batches' streaming inside the same launch.
// ---------------------------------------------------------------------------
__global__ void __launch_bounds__(256, 6) k_dots(const float* __restrict__ mem,
        const float* __restrict__ rw, const float* __restrict__ ww,
        const float* __restrict__ us, const float* __restrict__ fg,
        float* __restrict__ out) {
    int b = blockIdx.y;
    int t = threadIdx.x;
    int warp = t >> 5, lane = t & 31;   // 8 warps
    __shared__ union DU {
        struct { float sa[E]; float sb[E]; } d;
        struct {
            unsigned long long skey[M];   // 16KB
            float              ssu[M];    // 8KB
            unsigned int       sstart[257];
            unsigned int       scur[256];
        } a;
    } sm;
    __shared__ float sred[8];
    __shared__ float bc;
    __shared__ unsigned int swscan[8];
    __shared__ float swprod[8];
    __shared__ unsigned int s_tk;

    // ---------------- dots phase ----------------
    if (t < E) {
        sm.d.sa[t] = g_avec[(size_t)b*E + t];
        sm.d.sb[t] = g_bvec[(size_t)b*E + t];
    }
    __syncthreads();
    float4 a  = ((const float4*)sm.d.sa)[lane];
    float4 bb = ((const float4*)sm.d.sb)[lane];
    __syncthreads();   // everyone has a/bb in regs before union is reused
    const float4* mrow = (const float4*)(mem + (size_t)b*M*E);
    int mbase = blockIdx.x*128 + warp*16;
    #pragma unroll
    for (int g = 0; g < 4; g++) {
        int m0 = mbase + g*4;
        float4 v[4];
        #pragma unroll
        for (int k = 0; k < 4; k++)
            v[k] = mrow[(size_t)(m0 + k)*32 + lane];
        float ds[4], dr[4];
        #pragma unroll
        for (int k = 0; k < 4; k++) {
            ds[k] = v[k].x*a.x + v[k].y*a.y + v[k].z*a.z + v[k].w*a.w;
            dr[k] = v[k].x*bb.x + v[k].y*bb.y + v[k].z*bb.z + v[k].w*bb.w;
        }
        #pragma unroll
        for (int o = 16; o > 0; o >>= 1) {
            #pragma unroll
            for (int k = 0; k < 4; k++) {
                ds[k] += __shfl_down_sync(0xffffffffu, ds[k], o);
                dr[k] += __shfl_down_sync(0xffffffffu, dr[k], o);
            }
        }
        if (lane == 0) {
            #pragma unroll
            for (int k = 0; k < 4; k++) {
                g_scores[(size_t)b*M + m0 + k] = ds[k];
                g_rbase [(size_t)b*M + m0 + k] = dr[k];
            }
        }
    }

    // ---------------- ticket ----------------
    __threadfence();
    __syncthreads();
    if (t == 0) s_tk = atomicAdd(&g_done1[b], 1u);
    __syncthreads();
    if (s_tk != 15u) return;
    __threadfence();   // acquire: other blocks' scores/rbase now visible

    // ---------------- allocation + softmax tail ----------------
    size_t base = (size_t)b*M;
    int wid = warp;

    float u[8];
    {
        float4 U0 = ((const float4*)(us + base))[2*t], U1 = ((const float4*)(us + base))[2*t+1];
        float4 W0 = ((const float4*)(ww + base))[2*t], W1 = ((const float4*)(ww + base))[2*t+1];
        float4 F0 = ((const float4*)(fg + base))[2*t], F1 = ((const float4*)(fg + base))[2*t+1];
        float4 R0 = ((const float4*)(rw + base))[2*t], R1 = ((const float4*)(rw + base))[2*t+1];
        float uu[8] = {U0.x,U0.y,U0.z,U0.w, U1.x,U1.y,U1.z,U1.w};
        float wv[8] = {W0.x,W0.y,W0.z,W0.w, W1.x,W1.y,W1.z,W1.w};
        float ff[8] = {F0.x,F0.y,F0.z,F0.w, F1.x,F1.y,F1.z,F1.w};
        float rr[8] = {R0.x,R0.y,R0.z,R0.w, R1.x,R1.y,R1.z,R1.w};
        #pragma unroll
        for (int j = 0; j < 8; j++) {
            float uv = 1e-5f + (1.f - 1e-5f)*uu[j];
            uv = uv + wv[j] - uv*wv[j];
            uv *= (1.f - ff[j]*rr[j]);
            u[j] = uv;
        }
        ((float4*)(out + OFF_NU + base))[2*t]   = make_float4(u[0],u[1],u[2],u[3]);
        ((float4*)(out + OFF_NU + base))[2*t+1] = make_float4(u[4],u[5],u[6],u[7]);
    }

    // histogram over buckets floor(u*256) (monotone in u)
    sm.a.scur[t] = 0u;
    __syncthreads();
    int bkt[8];
    #pragma unroll
    for (int j = 0; j < 8; j++) {
        bkt[j] = min(255, max(0, (int)(u[j]*256.f)));
        atomicAdd(&sm.a.scur[bkt[j]], 1u);
    }
    __syncthreads();

    // exclusive additive scan of bin counts (shuffle-based)
    unsigned int cnt = sm.a.scur[t];
    unsigned int incl = cnt;
    #pragma unroll
    for (int o = 1; o < 32; o <<= 1) {
        unsigned int n = __shfl_up_sync(0xffffffffu, incl, o);
        if (lane >= o) incl += n;
    }
    if (lane == 31) swscan[wid] = incl;
    __syncthreads();
    if (t < 8) {
        unsigned int w = swscan[t];
        #pragma unroll
        for (int o = 1; o < 8; o <<= 1) {
            unsigned int n = __shfl_up_sync(0xffu, w, o);
            if (t >= o) w += n;
        }
        swscan[t] = w;
    }
    __syncthreads();
    unsigned int excl = incl - cnt + (wid ? swscan[wid-1] : 0u);
    sm.a.sstart[t] = excl;
    if (t == 0) sm.a.sstart[256] = M;
    sm.a.scur[t] = excl;
    __syncthreads();

    // scatter exact 64-bit keys (stable: low 11 bits = original index)
    #pragma unroll
    for (int j = 0; j < 8; j++) {
        unsigned long long key = ((unsigned long long)__float_as_uint(u[j]) << 11) | (unsigned)(8*t + j);
        unsigned int pos = atomicAdd(&sm.a.scur[bkt[j]], 1u);
        sm.a.skey[pos] = key;
    }
    __syncthreads();

    // rank within bucket (exact, stable)
    int p[8];
    #pragma unroll
    for (int j = 0; j < 8; j++) {
        unsigned long long key = ((unsigned long long)__float_as_uint(u[j]) << 11) | (unsigned)(8*t + j);
        unsigned int s0 = sm.a.sstart[bkt[j]], s1 = sm.a.sstart[bkt[j]+1];
        int r = 0;
        for (unsigned int c = s0; c < s1; c++)
            r += (sm.a.skey[c] < key) ? 1 : 0;
        p[j] = (int)s0 + r;
        sm.a.ssu[p[j]] = u[j];
    }
    __syncthreads();

    // inclusive cumprod over sorted u (shuffle scans; shift-based exclusive,
    // no division -> safe with underflowed products)
    float sv[8]; float prod = 1.f;
    #pragma unroll
    for (int j = 0; j < 8; j++) { sv[j] = sm.a.ssu[8*t + j]; prod *= sv[j]; }
    float fincl = prod;
    #pragma unroll
    for (int o = 1; o < 32; o <<= 1) {
        float n = __shfl_up_sync(0xffffffffu, fincl, o);
        if (lane >= o) fincl *= n;
    }
    if (lane == 31) swprod[wid] = fincl;
    __syncthreads();
    if (t < 8) {
        float w = swprod[t];
        #pragma unroll
        for (int o = 1; o < 8; o <<= 1) {
            float n = __shfl_up_sync(0xffu, w, o);
            if (t >= o) w *= n;
        }
        swprod[t] = w;
    }
    __syncthreads();
    float wex = __shfl_up_sync(0xffffffffu, fincl, 1);
    float prefix = ((lane == 0) ? 1.f : wex) * ((wid == 0) ? 1.f : swprod[wid-1]);
    float running = prefix;
    #pragma unroll
    for (int j = 0; j < 8; j++) { running *= sv[j]; sm.a.ssu[8*t + j] = running; }
    __syncthreads();
    float al[8];
    #pragma unroll
    for (int j = 0; j < 8; j++) al[j] = (1.f - u[j])*sm.a.ssu[p[j]];

    // softmax(scores); w = 0.5*(softmax + alloc)
    float sc[8];
    {
        float4 S0 = ((const float4*)(g_scores + base))[2*t], S1 = ((const float4*)(g_scores + base))[2*t+1];
        sc[0]=S0.x; sc[1]=S0.y; sc[2]=S0.z; sc[3]=S0.w;
        sc[4]=S1.x; sc[5]=S1.y; sc[6]=S1.z; sc[7]=S1.w;
    }
    float v = sc[0];
    #pragma unroll
    for (int j = 1; j < 8; j++) v = fmaxf(v, sc[j]);
    #pragma unroll
    for (int o = 16; o > 0; o >>= 1) v = fmaxf(v, __shfl_xor_sync(0xffffffffu, v, o));
    if (lane == 0) sred[wid] = v;
    __syncthreads();
    if (t < 8) {
        float xx = sred[t];
        #pragma unroll
        for (int o = 4; o > 0; o >>= 1) xx = fmaxf(xx, __shfl_xor_sync(0xffu, xx, o));
        if (t == 0) bc = xx;
    }
    __syncthreads();
    float mx = bc;
    float e[8], sum = 0.f;
    #pragma unroll
    for (int j = 0; j < 8; j++) { e[j] = __expf(sc[j] - mx); sum += e[j]; }
    v = sum;
    #pragma unroll
    for (int o = 16; o > 0; o >>= 1) v += __shfl_xor_sync(0xffffffffu, v, o);
    if (lane == 0) sred[wid] = v;
    __syncthreads();
    if (t < 8) {
        float xx = sred[t];
        #pragma unroll
        for (int o = 4; o > 0; o >>= 1) xx += __shfl_xor_sync(0xffu, xx, o);
        if (t == 0) bc = xx;
    }
    __syncthreads();
    float inv = 1.f/bc;
    float wgt[8];
    #pragma unroll
    for (int j = 0; j < 8; j++) wgt[j] = 0.5f*(e[j]*inv + al[j]);
    ((float4*)(out + OFF_NWW + base))[2*t]   = make_float4(wgt[0],wgt[1],wgt[2],wgt[3]);
    ((float4*)(out + OFF_NWW + base))[2*t+1] = make_float4(wgt[4],wgt[5],wgt[6],wgt[7]);
    __syncthreads();   // bc reuse guard

    // rscores = rbase + w*ce; softmax -> wr
    float ce = g_ce[b];
    {
        float4 R0 = ((const float4*)(g_rbase + base))[2*t], R1 = ((const float4*)(g_rbase + base))[2*t+1];
        sc[0]=R0.x; sc[1]=R0.y; sc[2]=R0.z; sc[3]=R0.w;
        sc[4]=R1.x; sc[5]=R1.y; sc[6]=R1.z; sc[7]=R1.w;
    }
    #pragma unroll
    for (int j = 0; j < 8; j++) sc[j] += wgt[j]*ce;
    v = sc[0];
    #pragma unroll
    for (int j = 1; j < 8; j++) v = fmaxf(v, sc[j]);
    #pragma unroll
    for (int o = 16; o > 0; o >>= 1) v = fmaxf(v, __shfl_xor_sync(0xffffffffu, v, o));
    if (lane == 0) sred[wid] = v;
    __syncthreads();
    if (t < 8) {
        float xx = sred[t];
        #pragma unroll
        for (int o = 4; o > 0; o >>= 1) xx = fmaxf(xx, __shfl_xor_sync(0xffu, xx, o));
        if (t == 0) bc = xx;
    }
    __syncthreads();
    mx = bc;
    sum = 0.f;
    #pragma unroll
    for (int j = 0; j < 8; j++) { e[j] = __expf(sc[j] - mx); sum += e[j]; }
    v = sum;
    #pragma unroll
    for (int o = 16; o > 0; o >>= 1) v += __shfl_xor_sync(0xffffffffu, v, o);
    if (lane == 0) sred[wid] = v;
    __syncthreads();
    if (t < 8) {
        float xx = sred[t];
        #pragma unroll
        for (int o = 4; o > 0; o >>= 1) xx += __shfl_xor_sync(0xffu, xx, o);
        if (t == 0) bc = xx;
    }
    __syncthreads();
    inv = 1.f/bc;
    ((float4*)(out + OFF_WR + base))[2*t]   = make_float4(e[0]*inv,e[1]*inv,e[2]*inv,e[3]*inv);
    ((float4*)(out + OFF_WR + base))[2*t+1] = make_float4(e[4]*inv,e[5]*inv,e[6]*inv,e[7]*inv);
}

// ---------------------------------------------------------------------------
// Kernel 2: passB streaming + (last block per batch) output projection tail.
// new_mem = mem + w*emb (write), pooled += wr*new_mem; last block computes
// output = O_w @ pooled + O_b. Reverse batch order for L2 reuse from k_dots.
// ---------------------------------------------------------------------------
__global__ void __launch_bounds__(256, 6) k_passB(const float* __restrict__ mem,
        const float* __restrict__ Ow, const float* __restrict__ Ob,
        float* __restrict__ out) {
    int b = B - 1 - blockIdx.y;
    int t = threadIdx.x;
    int warp = t >> 5, lane = t & 31;
    __shared__ __align__(16) float semb[E];
    __shared__ float spool[E];
    __shared__ unsigned int s_tk;
    if (t < E) {
        semb[t] = g_emb[(size_t)b*E + t];
        spool[t] = 0.f;
    }
    __syncthreads();
    float4 em = ((const float4*)semb)[lane];
    const float* wptr  = out + OFF_NWW + (size_t)b*M;
    const float* wrptr = out + OFF_WR  + (size_t)b*M;
    float4 p = make_float4(0.f, 0.f, 0.f, 0.f);
    int mbase = blockIdx.x*128 + warp*16;
    #pragma unroll 4
    for (int r = 0; r < 16; r++) {
        int m = mbase + r;
        float wv  = wptr[m];
        float wrv = wrptr[m];
        const float4* row = (const float4*)(mem + ((size_t)b*M + m)*E);
        float4 v = row[lane];
        float4 nm;
        nm.x = v.x + wv*em.x; nm.y = v.y + wv*em.y;
        nm.z = v.z + wv*em.z; nm.w = v.w + wv*em.w;
        ((float4*)(out + OFF_NM + ((size_t)b*M + m)*E))[lane] = nm;
        p.x += wrv*nm.x; p.y += wrv*nm.y; p.z += wrv*nm.z; p.w += wrv*nm.w;
    }
    atomicAdd(&spool[lane*4+0], p.x);
    atomicAdd(&spool[lane*4+1], p.y);
    atomicAdd(&spool[lane*4+2], p.z);
    atomicAdd(&spool[lane*4+3], p.w);
    __syncthreads();
    if (t < E)
        atomicAdd(&g_pooled[(size_t)b*E + t], spool[t]);

    // ---------------- ticket ----------------
    __threadfence();
    __syncthreads();
    if (t == 0) s_tk = atomicAdd(&g_done2[b], 1u);
    __syncthreads();
    if (s_tk != 15u) return;
    __threadfence();   // acquire: all pooled contributions visible

    // ---------------- output projection tail ----------------
    __shared__ __align__(16) float sp[E];
    if (t < E) sp[t] = g_pooled[(size_t)b*E + t];
    __syncthreads();
    float4 pv = ((const float4*)sp)[lane];
    int wid = warp;
    #pragma unroll
    for (int g = 0; g < 8; g++) {
        int o0 = wid*8 + g*64;
        float d[8];
        #pragma unroll
        for (int r = 0; r < 8; r++) {
            float4 wv = ((const float4*)(Ow + (size_t)(o0 + r)*E))[lane];
            d[r] = wv.x*pv.x + wv.y*pv.y + wv.z*pv.z + wv.w*pv.w;
        }
        #pragma unroll
        for (int o = 16; o > 0; o >>= 1) {
            #pragma unroll
            for (int r = 0; r < 8; r++)
                d[r] += __shfl_down_sync(0xffffffffu, d[r], o);
        }
        if (lane == 0) {
            #pragma unroll
            for (int r = 0; r < 8; r++)
                out[OFF_OUT + (size_t)b*OUT_D + o0 + r] = d[r] + Ob[o0 + r];
        }
    }
}

extern "C" void kernel_launch(void* const* d_in, const int* in_sizes, int n_in,
                              void* d_out, int out_size) {
    const float* rw  = (const float*)d_in[0];
    const float* ww  = (const float*)d_in[1];
    const float* us  = (const float*)d_in[2];
    const float* fg  = (const float*)d_in[3];
    const float* x   = (const float*)d_in[4];
    const float* q   = (const float*)d_in[5];
    const float* mem = (const float*)d_in[6];
    const float* Iw  = (const float*)d_in[7];
    const float* Ib  = (const float*)d_in[8];
    const float* W1w = (const float*)d_in[9];
    const float* W1b = (const float*)d_in[10];
    const float* W2w = (const float*)d_in[11];
    // d_in[12] = W2_b: per-batch constant, cancels in softmax
    const float* R1w = (const float*)d_in[13];
    const float* R1b = (const float*)d_in[14];
    const float* R2w = (const float*)d_in[15];
    // d_in[16] = R2_b: per-batch constant, cancels in softmax
    const float* Ow  = (const float*)d_in[17];
    const float* Ob  = (const float*)d_in[18];
    float* out = (float*)d_out;

    k_pre  <<<B, 128>>>(x, q, Iw, Ib, W1w, W1b, W2w, R1w, R1b, R2w);
    k_dots <<<dim3(M/128, B), 256>>>(mem, rw, ww, us, fg, out);
    k_passB<<<dim3(M/128, B), 256>>>(mem, Ow, Ob, out);
}

// round 16
// speedup vs baseline: 1.5028x; 1.5028x over previous
#include <cuda_runtime.h>
#include <cub/cub.cuh>

#define B 256
#define M 2048
#define E 128
#define IN_D 512
#define Q_D 512
#define OUT_D 512
#define H 64

// output layout (depth-first flatten of ((wr, nww, nu), output, new_memory))
#define OFF_WR  ((size_t)0)
#define OFF_NWW ((size_t)B*M)
#define OFF_NU  ((size_t)2*B*M)
#define OFF_OUT ((size_t)3*B*M)
#define OFF_NM  ((size_t)3*B*M + (size_t)B*OUT_D)

// scratch (device globals: no allocation allowed)
__device__ float g_emb[B*E];
__device__ float g_avec[B*E];
__device__ float g_bvec[B*E];
__device__ float g_ce[B];
__device__ float g_scores[B*M];
__device__ float g_rbase[B*M];
__device__ float g_pooled[B*E];

struct MulOp {
    __device__ __forceinline__ float operator()(const float& a, const float& b) const { return a*b; }
};

// ---------------------------------------------------------------------------
// Kernel 0: per-batch small GEMMs, k_out-style geometry (warp per output row,
// float4 loads, 4 independent rows in flight). 256 thr = 8 warps per batch.
//   emb = I_w@x+I_b; Wi = W1@emb+b; Rq = R1@q+b; avec = W2^T Wi;
//   bvec = R2^T Rq; ce = bvec.emb. Also zeroes pooled.
// ---------------------------------------------------------------------------
__global__ void __launch_bounds__(256) k_pre(
                      const float* __restrict__ x, const float* __restrict__ query,
                      const float* __restrict__ Iw, const float* __restrict__ Ib,
                      const float* __restrict__ W1w, const float* __restrict__ W1b,
                      const float* __restrict__ W2w,
                      const float* __restrict__ R1w, const float* __restrict__ R1b,
                      const float* __restrict__ R2w) {
    int b = blockIdx.x, t = threadIdx.x;
    int lane = t & 31, wid = t >> 5;             // 8 warps
    __shared__ __align__(16) float sx[IN_D];
    __shared__ __align__(16) float sq[Q_D];
    __shared__ __align__(16) float semb[E];
    __shared__ float sWi[H], sRq[H], sbv[E], sred[E];
    for (int i = t; i < IN_D; i += 256) sx[i] = x[(size_t)b*IN_D + i];
    for (int i = t; i < Q_D;  i += 256) sq[i] = query[(size_t)b*Q_D + i];
    if (t < E) g_pooled[(size_t)b*E + t] = 0.f;
    __syncthreads();

    // lane-resident x and q fragments (4 float4 each: elements lane+32j)
    float4 xv[4], qv[4];
    #pragma unroll
    for (int j = 0; j < 4; j++) {
        xv[j] = ((const float4*)sx)[lane + 32*j];
        qv[j] = ((const float4*)sq)[lane + 32*j];
    }

    // ---- emb: 128 rows of Iw (512 each); warp does 16 rows in 4 groups of 4
    #pragma unroll
    for (int g = 0; g < 4; g++) {
        int o0 = wid*16 + g*4;
        float d[4];
        #pragma unroll
        for (int r = 0; r < 4; r++) {
            const float4* wr = (const float4*)(Iw + (size_t)(o0 + r)*IN_D);
            float acc = 0.f;
            #pragma unroll
            for (int j = 0; j < 4; j++) {
                float4 wv = wr[lane + 32*j];
                acc += wv.x*xv[j].x + wv.y*xv[j].y + wv.z*xv[j].z + wv.w*xv[j].w;
            }
            d[r] = acc;
        }
        #pragma unroll
        for (int o = 16; o > 0; o >>= 1) {
            #pragma unroll
            for (int r = 0; r < 4; r++) d[r] += __shfl_down_sync(0xffffffffu, d[r], o);
        }
        if (lane == 0) {
            #pragma unroll
            for (int r = 0; r < 4; r++) {
                float e = d[r] + Ib[o0 + r];
                semb[o0 + r] = e;
                g_emb[(size_t)b*E + o0 + r] = e;
            }
        }
    }
    __syncthreads();

    // ---- Wi (64 rows of 128) and Rq (64 rows of 512): 8 rows per warp each
    float4 ev = ((const float4*)semb)[lane];
    #pragma unroll
    for (int g = 0; g < 2; g++) {
        int o0 = wid*8 + g*4;
        float d[4];
        #pragma unroll
        for (int r = 0; r < 4; r++) {
            float4 wv = ((const float4*)(W1w + (size_t)(o0 + r)*E))[lane];
            d[r] = wv.x*ev.x + wv.y*ev.y + wv.z*ev.z + wv.w*ev.w;
        }
        #pragma unroll
        for (int o = 16; o > 0; o >>= 1) {
            #pragma unroll
            for (int r = 0; r < 4; r++) d[r] += __shfl_down_sync(0xffffffffu, d[r], o);
        }
        if (lane == 0) {
            #pragma unroll
            for (int r = 0; r < 4; r++) sWi[o0 + r] = d[r] + W1b[o0 + r];
        }
    }
    #pragma unroll
    for (int g = 0; g < 2; g++) {
        int o0 = wid*8 + g*4;
        float d[4];
        #pragma unroll
        for (int r = 0; r < 4; r++) {
            const float4* wr = (const float4*)(R1w + (size_t)(o0 + r)*Q_D);
            float acc = 0.f;
            #pragma unroll
            for (int j = 0; j < 4; j++) {
                float4 wv = wr[lane + 32*j];
                acc += wv.x*qv[j].x + wv.y*qv[j].y + wv.z*qv[j].z + wv.w*qv[j].w;
            }
            d[r] = acc;
        }
        #pragma unroll
        for (int o = 16; o > 0; o >>= 1) {
            #pragma unroll
            for (int r = 0; r < 4; r++) d[r] += __shfl_down_sync(0xffffffffu, d[r], o);
        }
        if (lane == 0) {
            #pragma unroll
            for (int r = 0; r < 4; r++) sRq[o0 + r] = d[r] + R1b[o0 + r];
        }
    }
    __syncthreads();

    // ---- avec (threads 0..127) / bvec (threads 128..255): coalesced over E
    if (t < E) {
        float av = 0.f;
        #pragma unroll 8
        for (int h = 0; h < H; h++) av += sWi[h]*W2w[(size_t)h*E + t];
        g_avec[(size_t)b*E + t] = av;
    } else {
        int tt = t - E;
        float bv = 0.f;
        #pragma unroll 8
        for (int h = 0; h < H; h++) bv += sRq[h]*R2w[(size_t)h*E + tt];
        g_bvec[(size_t)b*E + tt] = bv;
        sbv[tt] = bv;
    }
    __syncthreads();
    if (t < E) sred[t] = sbv[t]*semb[t];
    __syncthreads();
    for (int s = 64; s > 0; s >>= 1) { if (t < s) sred[t] += sred[t+s]; __syncthreads(); }
    if (t == 0) g_ce[b] = sred[0];
}

// ---------------------------------------------------------------------------
// Streaming dots: grid (M/128, B), 256 thr, warp owns 16 rows in 4 groups.
//   scores = a_vec . mem_row,  rbase = b_vec . mem_row
// ---------------------------------------------------------------------------
__global__ void k_dots(const float* __restrict__ mem) {
    int b = blockIdx.y;
    int warp = threadIdx.x >> 5, lane = threadIdx.x & 31;   // 8 warps
    __shared__ __align__(16) float sa[E];
    __shared__ __align__(16) float sb[E];
    if (threadIdx.x < E) {
        sa[threadIdx.x] = g_avec[(size_t)b*E + threadIdx.x];
        sb[threadIdx.x] = g_bvec[(size_t)b*E + threadIdx.x];
    }
    __syncthreads();
    float4 a  = ((const float4*)sa)[lane];
    float4 bb = ((const float4*)sb)[lane];
    const float4* mrow = (const float4*)(mem + (size_t)b*M*E);
    int mbase = blockIdx.x*128 + warp*16;
    #pragma unroll
    for (int g = 0; g < 4; g++) {
        int m0 = mbase + g*4;
        float4 v[4];
        #pragma unroll
        for (int k = 0; k < 4; k++)
            v[k] = mrow[(size_t)(m0 + k)*32 + lane];
        float ds[4], dr[4];
        #pragma unroll
        for (int k = 0; k < 4; k++) {
            ds[k] = v[k].x*a.x + v[k].y*a.y + v[k].z*a.z + v[k].w*a.w;
            dr[k] = v[k].x*bb.x + v[k].y*bb.y + v[k].z*bb.z + v[k].w*bb.w;
        }
        #pragma unroll
        for (int o = 16; o > 0; o >>= 1) {
            #pragma unroll
            for (int k = 0; k < 4; k++) {
                ds[k] += __shfl_down_sync(0xffffffffu, ds[k], o);
                dr[k] += __shfl_down_sync(0xffffffffu, dr[k], o);
            }
        }
        if (lane == 0) {
            #pragma unroll
            for (int k = 0; k < 4; k++) {
                g_scores[(size_t)b*M + m0 + k] = ds[k];
                g_rbase [(size_t)b*M + m0 + k] = dr[k];
            }
        }
    }
}

// ---------------------------------------------------------------------------
// Per-batch fused allocation+softmax (256 thr, 8 elems/thread):
//   usage update -> new_usage; EXACT stable bucket argsort (64-bit key
//   (bits<<11)|idx == jnp.argsort); cumprod; alloc;
//   w = 0.5*(softmax(scores)+alloc) -> NWW; wr = softmax(rbase+w*ce) -> WR
// ---------------------------------------------------------------------------
typedef cub::BlockScan<unsigned int, 256> ScanU;
typedef cub::BlockScan<float, 256> ScanF;

__global__ void __launch_bounds__(256) k_allocsoft(
        const float* __restrict__ rw, const float* __restrict__ ww,
        const float* __restrict__ us, const float* __restrict__ fg,
        float* __restrict__ out) {
    int b = blockIdx.x, t = threadIdx.x;
    int lane = t & 31, wid = t >> 5;
    size_t base = (size_t)b*M;

    __shared__ union KU {
        unsigned long long       skey[M];   // 16KB (also scan temp space)
        typename ScanU::TempStorage su_t;
        typename ScanF::TempStorage sf_t;
    } smK;
    __shared__ float        ssu[M];         // sorted u, then cumprod in place
    __shared__ unsigned int sstart[257];
    __shared__ unsigned int scur[256];
    __shared__ float sred[8];
    __shared__ float bc;

    // ---- usage update ----
    float u[8];
    {
        float4 U0 = ((const float4*)(us + base))[2*t], U1 = ((const float4*)(us + base))[2*t+1];
        float4 W0 = ((const float4*)(ww + base))[2*t], W1 = ((const float4*)(ww + base))[2*t+1];
        float4 F0 = ((const float4*)(fg + base))[2*t], F1 = ((const float4*)(fg + base))[2*t+1];
        float4 R0 = ((const float4*)(rw + base))[2*t], R1 = ((const float4*)(rw + base))[2*t+1];
        float uu[8] = {U0.x,U0.y,U0.z,U0.w, U1.x,U1.y,U1.z,U1.w};
        float wv[8] = {W0.x,W0.y,W0.z,W0.w, W1.x,W1.y,W1.z,W1.w};
        float ff[8] = {F0.x,F0.y,F0.z,F0.w, F1.x,F1.y,F1.z,F1.w};
        float rr[8] = {R0.x,R0.y,R0.z,R0.w, R1.x,R1.y,R1.z,R1.w};
        #pragma unroll
        for (int j = 0; j < 8; j++) {
            float uv = 1e-5f + (1.f - 1e-5f)*uu[j];
            uv = uv + wv[j] - uv*wv[j];
            uv *= (1.f - ff[j]*rr[j]);
            u[j] = uv;
        }
        ((float4*)(out + OFF_NU + base))[2*t]   = make_float4(u[0],u[1],u[2],u[3]);
        ((float4*)(out + OFF_NU + base))[2*t+1] = make_float4(u[4],u[5],u[6],u[7]);
    }

    // ---- histogram over buckets floor(u*256) ----
    int bkt[8];
    scur[t] = 0;
    __syncthreads();
    #pragma unroll
    for (int j = 0; j < 8; j++) {
        bkt[j] = min(255, max(0, (int)(u[j]*256.f)));
        atomicAdd(&scur[bkt[j]], 1u);
    }
    __syncthreads();

    // ---- bin prefix sum ----
    unsigned int cnt = scur[t], st;
    ScanU(smK.su_t).ExclusiveSum(cnt, st);
    __syncthreads();
    sstart[t] = st;
    if (t == 0) sstart[256] = M;
    scur[t] = st;                 // scatter cursors
    __syncthreads();

    // ---- scatter exact 64-bit keys (stable: low 11 bits = original index) ----
    unsigned long long key[8];
    #pragma unroll
    for (int j = 0; j < 8; j++) {
        key[j] = ((unsigned long long)__float_as_uint(u[j]) << 11) | (unsigned)(8*t + j);
        unsigned int pos = atomicAdd(&scur[bkt[j]], 1u);
        smK.skey[pos] = key[j];
    }
    __syncthreads();

    // ---- rank within bucket (exact, stable) ----
    int p[8];
    #pragma unroll
    for (int j = 0; j < 8; j++) {
        unsigned int s0 = sstart[bkt[j]], s1 = sstart[bkt[j]+1];
        int r = 0;
        for (unsigned int c = s0; c < s1; c++)
            r += (smK.skey[c] < key[j]) ? 1 : 0;
        p[j] = (int)s0 + r;
        ssu[p[j]] = u[j];
    }
    __syncthreads();

    // ---- cumprod over sorted u (in place) ----
    float sv[8], cp[8];
    #pragma unroll
    for (int j = 0; j < 8; j++) sv[j] = ssu[8*t + j];
    __syncthreads();              // all ranking smK reads done before temp reuse
    ScanF(smK.sf_t).InclusiveScan(sv, cp, MulOp());
    __syncthreads();
    #pragma unroll
    for (int j = 0; j < 8; j++) ssu[8*t + j] = cp[j];
    __syncthreads();
    float al[8];
    #pragma unroll
    for (int j = 0; j < 8; j++) al[j] = (1.f - u[j])*ssu[p[j]];

    // ---- softmax(scores); w = 0.5*(softmax + alloc) ----
    float sc[8];
    {
        float4 S0 = ((const float4*)(g_scores + base))[2*t], S1 = ((const float4*)(g_scores + base))[2*t+1];
        sc[0]=S0.x; sc[1]=S0.y; sc[2]=S0.z; sc[3]=S0.w;
        sc[4]=S1.x; sc[5]=S1.y; sc[6]=S1.z; sc[7]=S1.w;
    }
    float v = sc[0];
    #pragma unroll
    for (int j = 1; j < 8; j++) v = fmaxf(v, sc[j]);
    #pragma unroll
    for (int o = 16; o > 0; o >>= 1) v = fmaxf(v, __shfl_xor_sync(0xffffffffu, v, o));
    if (lane == 0) sred[wid] = v;
    __syncthreads();
    if (t < 8) {
        float xx = sred[t];
        #pragma unroll
        for (int o = 4; o > 0; o >>= 1) xx = fmaxf(xx, __shfl_xor_sync(0xffu, xx, o));
        if (t == 0) bc = xx;
    }
    __syncthreads();
    float mx = bc;
    float e[8], sum = 0.f;
    #pragma unroll
    for (int j = 0; j < 8; j++) { e[j] = __expf(sc[j] - mx); sum += e[j]; }
    v = sum;
    #pragma unroll
    for (int o = 16; o > 0; o >>= 1) v += __shfl_xor_sync(0xffffffffu, v, o);
    if (lane == 0) sred[wid] = v;
    __syncthreads();
    if (t < 8) {
        float xx = sred[t];
        #pragma unroll
        for (int o = 4; o > 0; o >>= 1) xx += __shfl_xor_sync(0xffu, xx, o);
        if (t == 0) bc = xx;
    }
    __syncthreads();
    float inv = 1.f/bc;
    float wgt[8];
    #pragma unroll
    for (int j = 0; j < 8; j++) wgt[j] = 0.5f*(e[j]*inv + al[j]);
    ((float4*)(out + OFF_NWW + base))[2*t]   = make_float4(wgt[0],wgt[1],wgt[2],wgt[3]);
    ((float4*)(out + OFF_NWW + base))[2*t+1] = make_float4(wgt[4],wgt[5],wgt[6],wgt[7]);
    __syncthreads();   // bc reuse guard

    // ---- rscores = rbase + w*ce; softmax -> wr ----
    float ce = g_ce[b];
    {
        float4 R0 = ((const float4*)(g_rbase + base))[2*t], R1 = ((const float4*)(g_rbase + base))[2*t+1];
        sc[0]=R0.x; sc[1]=R0.y; sc[2]=R0.z; sc[3]=R0.w;
        sc[4]=R1.x; sc[5]=R1.y; sc[6]=R1.z; sc[7]=R1.w;
    }
    #pragma unroll
    for (int j = 0; j < 8; j++) sc[j] += wgt[j]*ce;
    v = sc[0];
    #pragma unroll
    for (int j = 1; j < 8; j++) v = fmaxf(v, sc[j]);
    #pragma unroll
    for (int o = 16; o > 0; o >>= 1) v = fmaxf(v, __shfl_xor_sync(0xffffffffu, v, o));
    if (lane == 0) sred[wid] = v;
    __syncthreads();
    if (t < 8) {
        float xx = sred[t];
        #pragma unroll
        for (int o = 4; o > 0; o >>= 1) xx = fmaxf(xx, __shfl_xor_sync(0xffu, xx, o));
        if (t == 0) bc = xx;
    }
    __syncthreads();
    mx = bc;
    sum = 0.f;
    #pragma unroll
    for (int j = 0; j < 8; j++) { e[j] = __expf(sc[j] - mx); sum += e[j]; }
    v = sum;
    #pragma unroll
    for (int o = 16; o > 0; o >>= 1) v += __shfl_xor_sync(0xffffffffu, v, o);
    if (lane == 0) sred[wid] = v;
    __syncthreads();
    if (t < 8) {
        float xx = sred[t];
        #pragma unroll
        for (int o = 4; o > 0; o >>= 1) xx += __shfl_xor_sync(0xffu, xx, o);
        if (t == 0) bc = xx;
    }
    __syncthreads();
    inv = 1.f/bc;
    ((float4*)(out + OFF_WR + base))[2*t]   = make_float4(e[0]*inv,e[1]*inv,e[2]*inv,e[3]*inv);
    ((float4*)(out + OFF_WR + base))[2*t+1] = make_float4(e[4]*inv,e[5]*inv,e[6]*inv,e[7]*inv);
}

// ---------------------------------------------------------------------------
// Pass B: new_mem = mem + w*emb (write), pooled += wr*new_mem.
// Reverse batch order: tail of `mem` is still L2-resident from k_dots.
// ---------------------------------------------------------------------------
__global__ void k_passB(const float* __restrict__ mem, float* __restrict__ out) {
    int b = B - 1 - blockIdx.y;
    int warp = threadIdx.x >> 5, lane = threadIdx.x & 31;
    __shared__ __align__(16) float semb[E];
    __shared__ float spool[E];
    if (threadIdx.x < E) {
        semb[threadIdx.x] = g_emb[(size_t)b*E + threadIdx.x];
        spool[threadIdx.x] = 0.f;
    }
    __syncthreads();
    float4 em = ((const float4*)semb)[lane];
    const float* wptr  = out + OFF_NWW + (size_t)b*M;
    const float* wrptr = out + OFF_WR  + (size_t)b*M;
    float4 p = make_float4(0.f, 0.f, 0.f, 0.f);
    int mbase = blockIdx.x*128 + warp*16;
    #pragma unroll 4
    for (int r = 0; r < 16; r++) {
        int m = mbase + r;
        float wv  = wptr[m];
        float wrv = wrptr[m];
        const float4* row = (const float4*)(mem + ((size_t)b*M + m)*E);
        float4 v = row[lane];
        float4 nm;
        nm.x = v.x + wv*em.x; nm.y = v.y + wv*em.y;
        nm.z = v.z + wv*em.z; nm.w = v.w + wv*em.w;
        ((float4*)(out + OFF_NM + ((size_t)b*M + m)*E))[lane] = nm;
        p.x += wrv*nm.x; p.y += wrv*nm.y; p.z += wrv*nm.z; p.w += wrv*nm.w;
    }
    atomicAdd(&spool[lane*4+0], p.x);
    atomicAdd(&spool[lane*4+1], p.y);
    atomicAdd(&spool[lane*4+2], p.z);
    atomicAdd(&spool[lane*4+3], p.w);
    __syncthreads();
    if (threadIdx.x < E)
        atomicAdd(&g_pooled[(size_t)b*E + threadIdx.x], spool[threadIdx.x]);
}

// ---------------------------------------------------------------------------
// Output projection: grid (8, B), warp per output row, 8 rows per warp.
// ---------------------------------------------------------------------------
__global__ void k_out(const float* __restrict__ Ow, const float* __restrict__ Ob,
                      float* __restrict__ out) {
    int b = blockIdx.y, chunk = blockIdx.x;
    int lane = threadIdx.x & 31, wid = threadIdx.x >> 5;   // 8 warps
    __shared__ __align__(16) float sp[E];
    if (threadIdx.x < E) sp[threadIdx.x] = g_pooled[(size_t)b*E + threadIdx.x];
    __syncthreads();
    float4 pv = ((const float4*)sp)[lane];
    int o0 = chunk*64 + wid*8;
    float d[8];
    #pragma unroll
    for (int r = 0; r < 8; r++) {
        float4 wv = ((const float4*)(Ow + (size_t)(o0 + r)*E))[lane];
        d[r] = wv.x*pv.x + wv.y*pv.y + wv.z*pv.z + wv.w*pv.w;
    }
    #pragma unroll
    for (int o = 16; o > 0; o >>= 1) {
        #pragma unroll
        for (int r = 0; r < 8; r++)
            d[r] += __shfl_down_sync(0xffffffffu, d[r], o);
    }
    if (lane == 0) {
        #pragma unroll
        for (int r = 0; r < 8; r++)
            out[OFF_OUT + (size_t)b*OUT_D + o0 + r] = d[r] + Ob[o0 + r];
    }
}

extern "C" void kernel_launch(void* const* d_in, const int* in_sizes, int n_in,
                              void* d_out, int out_size) {
    const float* rw  = (const float*)d_in[0];
    const float* ww  = (const float*)d_in[1];
    const float* us  = (const float*)d_in[2];
    const float* fg  = (const float*)d_in[3];
    const float* x   = (const float*)d_in[4];
    const float* q   = (const float*)d_in[5];
    const float* mem = (const float*)d_in[6];
    const float* Iw  = (const float*)d_in[7];
    const float* Ib  = (const float*)d_in[8];
    const float* W1w = (const float*)d_in[9];
    const float* W1b = (const float*)d_in[10];
    const float* W2w = (const float*)d_in[11];
    // d_in[12] = W2_b: per-batch constant, cancels in softmax
    const float* R1w = (const float*)d_in[13];
    const float* R1b = (const float*)d_in[14];
    const float* R2w = (const float*)d_in[15];
    // d_in[16] = R2_b: per-batch constant, cancels in softmax
    const float* Ow  = (const float*)d_in[17];
    const float* Ob  = (const float*)d_in[18];
    float* out = (float*)d_out;

    k_pre      <<<B, 256>>>(x, q, Iw, Ib, W1w, W1b, W2w, R1w, R1b, R2w);
    k_dots     <<<dim3(M/128, B), 256>>>(mem);
    k_allocsoft<<<B, 256>>>(rw, ww, us, fg, out);
    k_passB    <<<dim3(M/128, B), 256>>>(mem, out);
    k_out      <<<dim3(8, B), 256>>>(Ow, Ob, out);
}